// round 17
// baseline (speedup 1.0000x reference)
#include <cuda_runtime.h>

#define D_DIM 256
#define NCLS 100
#define NCTA 128
#define NTHR 512
#define GSIZE (NCLS * D_DIM)      // 25600 floats = 100 KB per copy

// Scratch (__device__ globals; allocation forbidden). g_cnt self-resets each
// barrier; g_gen increments monotonically (2/launch) -> replay-deterministic.
__device__ __align__(16) float g_part[(size_t)NCTA * GSIZE];
__device__ __align__(16) float s_part[(size_t)NCTA * D_DIM];
__device__ float t_part[NCTA];
__device__ double sumsq_cls[NCLS];
__device__ float s_red[D_DIM];
__device__ unsigned g_cnt = 0;
__device__ unsigned g_gen = 0;

__device__ __forceinline__ void grid_barrier(unsigned target) {
    __syncthreads();
    if (threadIdx.x == 0) {
        __threadfence();
        unsigned old = atomicAdd(&g_cnt, 1u);
        if (old == NCTA - 1) {
            atomicExch(&g_cnt, 0u);   // reset BEFORE release
            __threadfence();
            atomicAdd(&g_gen, 1u);    // release
        } else {
            while (atomicAdd(&g_gen, 0u) < target) { }
        }
        __threadfence();
    }
    __syncthreads();
}

// ---------------------------------------------------------------------------
// Fused: 128 CTAs x 512 threads, 1 CTA/SM (200 KB smem) -> all resident.
// ---------------------------------------------------------------------------
__global__ void __launch_bounds__(NTHR)
k_fused(const float* __restrict__ feat,
        const void* __restrict__ label_raw, int B,
        float* __restrict__ out) {
    extern __shared__ float sG[];              // [2 * GSIZE] = 200 KB
    __shared__ float sS[NTHR];
    __shared__ float red[NTHR / 32];
    __shared__ float4 svA[8][D_DIM / 4];       // phase-2 class combine (8 KB)
    __shared__ float  svB[16][32];             // phase-2 s combine (2 KB)
    __shared__ double redd[NTHR / 32];
    __shared__ int s_is64;
    __shared__ unsigned s_gen0;

    const int tid = threadIdx.x;
    const int col = tid & 255;
    const int h   = tid >> 8;
    const int cta = blockIdx.x;

    if (tid == 0) s_gen0 = atomicAdd(&g_gen, 0u);  // stable until barrier 1

    // zero both smem copies (STS.128)
    {
        float4* z = (float4*)sG;
        #pragma unroll 5
        for (int i = tid; i < 2 * GSIZE / 4; i += NTHR)
            z[i] = make_float4(0.f, 0.f, 0.f, 0.f);
    }

    // parallel label-dtype sniff (int64 vs silently-downgraded int32)
    if (tid < 32) {
        const unsigned long long* p = (const unsigned long long*)label_raw;
        int n = (B < 16) ? B : 16;
        int bad = (tid < n) && (p[tid] >= 100ULL);
        unsigned m = __ballot_sync(0xFFFFFFFFu, bad);
        if (tid == 0) s_is64 = (m == 0u);
    }
    __syncthreads();
    const int is64 = s_is64;

    // ---------------- Phase 1: class-sum accumulation ----------------
    float* myG = sG + h * GSIZE;
    const int rows = (B + NCTA - 1) / NCTA;    // 64 for B=8192
    const int base = cta * rows;
    const int end  = (base + rows < B) ? (base + rows) : B;
    const int hr   = (rows + 1) >> 1;          // 32
    const int r0   = base + h * hr;
    int r1 = r0 + hr; if (r1 > end) r1 = end;

    float t = 0.0f, s = 0.0f;

    if (is64) {
        const long long* lab = (const long long*)label_raw;
        int r = r0;
        for (; r + 8 <= r1; r += 8) {
            float v0 = feat[(size_t)(r + 0) * D_DIM + col];
            float v1 = feat[(size_t)(r + 1) * D_DIM + col];
            float v2 = feat[(size_t)(r + 2) * D_DIM + col];
            float v3 = feat[(size_t)(r + 3) * D_DIM + col];
            float v4 = feat[(size_t)(r + 4) * D_DIM + col];
            float v5 = feat[(size_t)(r + 5) * D_DIM + col];
            float v6 = feat[(size_t)(r + 6) * D_DIM + col];
            float v7 = feat[(size_t)(r + 7) * D_DIM + col];
            int l0 = (int)lab[r + 0], l1 = (int)lab[r + 1];
            int l2 = (int)lab[r + 2], l3 = (int)lab[r + 3];
            int l4 = (int)lab[r + 4], l5 = (int)lab[r + 5];
            int l6 = (int)lab[r + 6], l7 = (int)lab[r + 7];
            t = fmaf(v0, v0, t);  s += v0;  myG[l0 * D_DIM + col] += v0;
            t = fmaf(v1, v1, t);  s += v1;  myG[l1 * D_DIM + col] += v1;
            t = fmaf(v2, v2, t);  s += v2;  myG[l2 * D_DIM + col] += v2;
            t = fmaf(v3, v3, t);  s += v3;  myG[l3 * D_DIM + col] += v3;
            t = fmaf(v4, v4, t);  s += v4;  myG[l4 * D_DIM + col] += v4;
            t = fmaf(v5, v5, t);  s += v5;  myG[l5 * D_DIM + col] += v5;
            t = fmaf(v6, v6, t);  s += v6;  myG[l6 * D_DIM + col] += v6;
            t = fmaf(v7, v7, t);  s += v7;  myG[l7 * D_DIM + col] += v7;
        }
        for (; r < r1; ++r) {
            float v = feat[(size_t)r * D_DIM + col];
            int l = (int)lab[r];
            t = fmaf(v, v, t);  s += v;  myG[l * D_DIM + col] += v;
        }
    } else {
        const int* lab = (const int*)label_raw;
        int r = r0;
        for (; r + 8 <= r1; r += 8) {
            float v0 = feat[(size_t)(r + 0) * D_DIM + col];
            float v1 = feat[(size_t)(r + 1) * D_DIM + col];
            float v2 = feat[(size_t)(r + 2) * D_DIM + col];
            float v3 = feat[(size_t)(r + 3) * D_DIM + col];
            float v4 = feat[(size_t)(r + 4) * D_DIM + col];
            float v5 = feat[(size_t)(r + 5) * D_DIM + col];
            float v6 = feat[(size_t)(r + 6) * D_DIM + col];
            float v7 = feat[(size_t)(r + 7) * D_DIM + col];
            int l0 = lab[r + 0], l1 = lab[r + 1], l2 = lab[r + 2], l3 = lab[r + 3];
            int l4 = lab[r + 4], l5 = lab[r + 5], l6 = lab[r + 6], l7 = lab[r + 7];
            t = fmaf(v0, v0, t);  s += v0;  myG[l0 * D_DIM + col] += v0;
            t = fmaf(v1, v1, t);  s += v1;  myG[l1 * D_DIM + col] += v1;
            t = fmaf(v2, v2, t);  s += v2;  myG[l2 * D_DIM + col] += v2;
            t = fmaf(v3, v3, t);  s += v3;  myG[l3 * D_DIM + col] += v3;
            t = fmaf(v4, v4, t);  s += v4;  myG[l4 * D_DIM + col] += v4;
            t = fmaf(v5, v5, t);  s += v5;  myG[l5 * D_DIM + col] += v5;
            t = fmaf(v6, v6, t);  s += v6;  myG[l6 * D_DIM + col] += v6;
            t = fmaf(v7, v7, t);  s += v7;  myG[l7 * D_DIM + col] += v7;
        }
        for (; r < r1; ++r) {
            float v = feat[(size_t)r * D_DIM + col];
            int l = lab[r];
            t = fmaf(v, v, t);  s += v;  myG[l * D_DIM + col] += v;
        }
    }
    sS[tid] = s;
    __syncthreads();

    // merge halves, write this CTA's partial (stays dirty in L2)
    {
        const float4* a = (const float4*)sG;
        const float4* b = (const float4*)(sG + GSIZE);
        float4* gp4 = (float4*)(g_part + (size_t)cta * GSIZE);
        #pragma unroll 4
        for (int i = tid; i < GSIZE / 4; i += NTHR) {
            float4 x = a[i], y = b[i];
            gp4[i] = make_float4(x.x + y.x, x.y + y.y, x.z + y.z, x.w + y.w);
        }
    }
    if (h == 0)
        s_part[(size_t)cta * D_DIM + col] = sS[col] + sS[col + 256];

    // block-reduce t (fixed order)
    #pragma unroll
    for (int o = 16; o > 0; o >>= 1) t += __shfl_down_sync(0xFFFFFFFFu, t, o);
    if ((tid & 31) == 0) red[tid >> 5] = t;
    __syncthreads();
    if (tid == 0) {
        float v = 0.0f;
        #pragma unroll
        for (int w = 0; w < NTHR / 32; ++w) v += red[w];
        t_part[cta] = v;
    }

    // ---------------- Barrier 1 ----------------
    grid_barrier(s_gen0 + 1);

    // ---------------- Phase 2 (reads hit L2 dirty lines) ----------------
    if (cta < NCLS) {
        // class cta: 8 p-groups x 64 float4 columns, 16 LDG.128 per thread
        const int c4 = tid & 63;
        const int pg = tid >> 6;               // 0..7
        const float4* bp = (const float4*)g_part
                         + (size_t)(pg * 16) * (GSIZE / 4)
                         + (size_t)cta * (D_DIM / 4) + c4;
        float4 acc = make_float4(0.f, 0.f, 0.f, 0.f);
        #pragma unroll
        for (int p = 0; p < 16; ++p) {
            float4 v = bp[(size_t)p * (GSIZE / 4)];
            acc.x += v.x; acc.y += v.y; acc.z += v.z; acc.w += v.w;
        }
        svA[pg][c4] = acc;
        __syncthreads();
        if (tid < 64) {
            float4 g = svA[0][tid];
            #pragma unroll
            for (int p = 1; p < 8; ++p) {
                float4 v = svA[p][tid];
                g.x += v.x; g.y += v.y; g.z += v.z; g.w += v.w;
            }
            double sq = (double)g.x * g.x + (double)g.y * g.y
                      + (double)g.z * g.z + (double)g.w * g.w;
            #pragma unroll
            for (int o = 16; o > 0; o >>= 1)
                sq += __shfl_down_sync(0xFFFFFFFFu, sq, o);
            if ((tid & 31) == 0) redd[tid >> 5] = sq;
        }
        __syncthreads();
        if (tid == 0) sumsq_cls[cta] = redd[0] + redd[1];
    } else if (cta < 108) {
        // s reduction: 8 CTAs x 32 columns, 16 p-groups x 8 partials each
        const int cl = tid & 31;
        const int pg = tid >> 5;               // 0..15
        const int colg = (cta - NCLS) * 32 + cl;
        float acc = 0.0f;
        #pragma unroll
        for (int p = 0; p < 8; ++p)
            acc += s_part[(size_t)(pg * 8 + p) * D_DIM + colg];
        svB[pg][cl] = acc;
        __syncthreads();
        if (tid < 32) {
            float v = svB[0][tid];
            #pragma unroll
            for (int p = 1; p < 16; ++p) v += svB[p][tid];
            s_red[(cta - NCLS) * 32 + tid] = v;
        }
    }

    // ---------------- Barrier 2 ----------------
    grid_barrier(s_gen0 + 2);

    // ---------------- Final combine (CTA 0, fp64, fixed order) ----------------
    if (cta == 0) {
        double val = 0.0;
        if (tid < D_DIM) {
            double sv = (double)s_red[tid];
            val = 0.5 * sv * sv;
            if (tid < NCTA) val += (double)t_part[tid];
        }
        if (tid < NCLS) val -= 1.5 * sumsq_cls[tid];

        #pragma unroll
        for (int o = 16; o > 0; o >>= 1)
            val += __shfl_down_sync(0xFFFFFFFFu, val, o);
        if ((tid & 31) == 0) redd[tid >> 5] = val;
        __syncthreads();
        if (tid == 0) {
            double v = 0.0;
            #pragma unroll
            for (int w = 0; w < NTHR / 32; ++w) v += redd[w];
            out[0] = (float)v;
        }
    }
}

// ---------------------------------------------------------------------------
extern "C" void kernel_launch(void* const* d_in, const int* in_sizes, int n_in,
                              void* d_out, int out_size) {
    const float* feat = (const float*)d_in[0];
    const void* label = d_in[1];
    const int B = in_sizes[1];

    cudaFuncSetAttribute(k_fused, cudaFuncAttributeMaxDynamicSharedMemorySize,
                         2 * GSIZE * (int)sizeof(float));

    k_fused<<<NCTA, NTHR, 2 * GSIZE * sizeof(float)>>>(feat, label, B,
                                                       (float*)d_out);
}